// round 2
// baseline (speedup 1.0000x reference)
#include <cuda_runtime.h>
#include <cstdint>

// Shapes for PairwiseEmbeddings: B=2, L=256, H=256, A=32, P=64
#define LL   256
#define NB   2
#define NBI  512          // B*L
#define AA   32
#define PP   64
#define HH   256
#define CP   2048         // A*P : cp = c*64 + p  (c-major, p fastest)

// Scratch (no cudaMalloc allowed): ~4.3 MB total
__device__ float g_h [NBI * AA];        // h[bi][a]                64 KB
__device__ float g_wT[HH * AA];         // in_w transposed [k][a]  32 KB
__device__ float g_W2[AA * CP];         // W2[a][c*64+p]          256 KB
__device__ float g_M [NBI * CP];        // M[bi][c*64+p]            4 MB

// ---------------------------------------------------------------------------
// Prep: transpose out_w -> W2[a][c*64+p], transpose in_w -> wT[k][a]
// ---------------------------------------------------------------------------
__global__ void k_prep(const float* __restrict__ out_w,
                       const float* __restrict__ in_w) {
    int idx = blockIdx.x * 256 + threadIdx.x;       // grid covers 65536
    if (idx < PP * AA * AA) {
        int p = idx >> 10;          // out_w flat = p*1024 + a*32 + c
        int a = (idx >> 5) & 31;
        int c = idx & 31;
        g_W2[a * CP + c * PP + p] = out_w[idx];
    }
    if (idx < AA * HH) {
        int a = idx >> 8;           // in_w flat = a*256 + k
        int k = idx & 255;
        g_wT[k * AA + a] = in_w[idx];
    }
}

// ---------------------------------------------------------------------------
// K1: h[bi][a] = sum_k x[bi][k] * in_w[a][k] + in_b[a]
// One block per bi row. thread t: a = t%32 (coalesced wT), kc = t/32 partials.
// ---------------------------------------------------------------------------
__global__ void k_h(const float* __restrict__ x,
                    const float* __restrict__ in_b) {
    __shared__ float red[256];
    int t  = threadIdx.x;
    int bi = blockIdx.x;
    int a  = t & 31;
    int kc = t >> 5;                 // 0..7
    const float* xr = x + bi * HH + kc * 32;     // uniform per warp
    const float* wr = g_wT + (kc * 32) * AA + a; // coalesced over lanes
    float acc = 0.f;
#pragma unroll
    for (int k = 0; k < 32; k++)
        acc += xr[k] * wr[k * AA];
    red[t] = acc;
    __syncthreads();
    if (t < 32) {
        float s = in_b[t];
#pragma unroll
        for (int q = 0; q < 8; q++) s += red[q * 32 + t];
        g_h[bi * AA + t] = s;
    }
}

// ---------------------------------------------------------------------------
// K2: M[bi][cp] = sum_a h[bi][a] * W2[a][cp]
// grid (32 bi-tiles of 16, 8 cp-tiles of 256); thread owns one cp, 16 bi acc.
// W2 loads coalesced + L2 resident; h broadcast from smem.
// ---------------------------------------------------------------------------
__global__ void k_m() {
    __shared__ float hs[16 * AA];    // 2 KB
    int t   = threadIdx.x;
    int bi0 = blockIdx.x * 16;
    int cp  = blockIdx.y * 256 + t;

    for (int idx = t; idx < 16 * AA; idx += 256)
        hs[idx] = g_h[bi0 * AA + idx];
    __syncthreads();

    float acc[16];
#pragma unroll
    for (int i = 0; i < 16; i++) acc[i] = 0.f;

#pragma unroll
    for (int a = 0; a < AA; a++) {
        float w = g_W2[a * CP + cp];
#pragma unroll
        for (int i = 0; i < 16; i++)
            acc[i] = fmaf(hs[i * AA + a], w, acc[i]);
    }
#pragma unroll
    for (int i = 0; i < 16; i++)
        g_M[(bi0 + i) * CP + cp] = acc[i];
}

// ---------------------------------------------------------------------------
// K3 (dominant): out[bi][j][p] = sum_c M[bi][c][p] * h[b][j][c] + table[d][p]
// One block per bi (512 blocks), thread = j (256). 64 p accumulators packed
// as 32 f32x2 pairs -> fma.rn.f32x2 (FFMA2) for 2x fp32 throughput.
//
// Key change vs R1: M operands are loaded from shared directly as ulonglong2
// (same broadcast LDS.128, but the dest register quad IS the two packed f32x2
// operands) — eliminates the 32 pack-MOVs per c that made R1 alu-pipe-bound.
// ---------------------------------------------------------------------------
__global__ void __launch_bounds__(256, 2)
k_main(const float* __restrict__ pos_w,
       const float* __restrict__ pos_b,
       const float* __restrict__ out_b,
       float* __restrict__ out) {
    __shared__ __align__(16) float ms [AA * PP];   // Mt[c][p]   8 KB
    __shared__ float hsj[LL * 33];                 // padded h  33.8 KB
    __shared__ __align__(16) float ps [17 * 68];   // pos table 4.6 KB

    int t  = threadIdx.x;
    int bi = blockIdx.x;
    int b  = bi >> 8;
    int i  = bi & 255;

    // M slice for this (b,i): contiguous, coalesced
    for (int idx = t; idx < AA * PP; idx += 256)
        ms[idx] = g_M[bi * CP + idx];

    // h rows for batch b, staged padded (stride 33) for conflict-free reads
    const float* hb = &g_h[(size_t)b * LL * AA];
#pragma unroll
    for (int k = 0; k < 32; k++) {
        int idx = k * 256 + t;                 // 8192 floats
        hsj[(idx >> 5) * 33 + (idx & 31)] = hb[idx];
    }

    // fold out_b + pos_b into pos table: ps[d][p]
    for (int idx = t; idx < 17 * 64; idx += 256) {
        int d = idx >> 6, p = idx & 63;
        ps[d * 68 + p] = pos_w[p * 17 + d] + pos_b[p] + out_b[p];
    }
    __syncthreads();

    int j = t;
    float hr[32];
#pragma unroll
    for (int c = 0; c < 32; c++) hr[c] = hsj[j * 33 + c];

    unsigned long long acc[32];
#pragma unroll
    for (int k = 0; k < 32; k++) acc[k] = 0ULL;

#pragma unroll
    for (int c = 0; c < 32; c++) {
        unsigned int hu = __float_as_uint(hr[c]);
        unsigned long long h2;
        asm("mov.b64 %0, {%1, %1};" : "=l"(h2) : "r"(hu));
        // ms rows are 16B-aligned (PP*4 = 256B row stride); read as packed
        // 64-bit pairs: one ulonglong2 = LDS.128 whose register quad is
        // directly the two f32x2 operands (no pack MOVs).
        const ulonglong2* mrow =
            reinterpret_cast<const ulonglong2*>(&ms[c * PP]);
#pragma unroll
        for (int q = 0; q < 16; q++) {
            ulonglong2 m = mrow[q];             // broadcast LDS.128
            asm("fma.rn.f32x2 %0, %1, %2, %0;"
                : "+l"(acc[2 * q])     : "l"(m.x), "l"(h2));
            asm("fma.rn.f32x2 %0, %1, %2, %0;"
                : "+l"(acc[2 * q + 1]) : "l"(m.y), "l"(h2));
        }
    }

    // epilogue: add rel-pos row, vectorized store
    int d = i - j;
    d = (d < -8) ? -8 : ((d > 8) ? 8 : d);
    d += 8;
    const float* pr = &ps[d * 68];
    float* ob = out + ((size_t)bi * LL + j) * PP;
#pragma unroll
    for (int q = 0; q < 16; q++) {
        unsigned int x0, x1, x2, x3;
        asm("mov.b64 {%0, %1}, %2;" : "=r"(x0), "=r"(x1) : "l"(acc[2 * q]));
        asm("mov.b64 {%0, %1}, %2;" : "=r"(x2), "=r"(x3) : "l"(acc[2 * q + 1]));
        float4 v;
        v.x = __uint_as_float(x0) + pr[4 * q + 0];
        v.y = __uint_as_float(x1) + pr[4 * q + 1];
        v.z = __uint_as_float(x2) + pr[4 * q + 2];
        v.w = __uint_as_float(x3) + pr[4 * q + 3];
        reinterpret_cast<float4*>(ob)[q] = v;
    }
}

// ---------------------------------------------------------------------------
// Launch
// inputs (metadata order): inputs_embeds, in_w, in_b, out_w, out_b, pos_w, pos_b
// ---------------------------------------------------------------------------
extern "C" void kernel_launch(void* const* d_in, const int* in_sizes, int n_in,
                              void* d_out, int out_size) {
    const float* x     = (const float*)d_in[0];
    const float* in_w  = (const float*)d_in[1];
    const float* in_b  = (const float*)d_in[2];
    const float* out_w = (const float*)d_in[3];
    const float* out_b = (const float*)d_in[4];
    const float* pos_w = (const float*)d_in[5];
    const float* pos_b = (const float*)d_in[6];
    float* out = (float*)d_out;

    k_prep<<<256, 256>>>(out_w, in_w);
    k_h   <<<NBI, 256>>>(x, in_b);
    k_m   <<<dim3(32, 8), 256>>>();
    k_main<<<NBI, 256>>>(pos_w, pos_b, out_b, out);
}

// round 4
// speedup vs baseline: 1.2119x; 1.2119x over previous
#include <cuda_runtime.h>
#include <cstdint>

// Shapes for PairwiseEmbeddings: B=2, L=256, H=256, A=32, P=64
#define LL   256
#define NB   2
#define NBI  512          // B*L
#define AA   32
#define PP   64
#define HH   256
#define CP   2048         // A*P : cp = c*64 + p  (c-major, p fastest)

// Scratch (no cudaMalloc allowed): ~4.4 MB total
__device__ float g_h [NBI * AA];        // h[bi][a]                64 KB
__device__ float g_hT[NB * AA * LL];    // hT[b][c][j]             64 KB
__device__ float g_wT[HH * AA];         // in_w transposed [k][a]  32 KB
__device__ float g_W2[AA * CP];         // W2[a][c*64+p]          256 KB
__device__ float g_M [NBI * CP];        // M[bi][c*64+p]            4 MB

// ---------------------------------------------------------------------------
// Prep: transpose out_w -> W2[a][c*64+p], transpose in_w -> wT[k][a]
// ---------------------------------------------------------------------------
__global__ void k_prep(const float* __restrict__ out_w,
                       const float* __restrict__ in_w) {
    int idx = blockIdx.x * 256 + threadIdx.x;       // grid covers 65536
    if (idx < PP * AA * AA) {
        int p = idx >> 10;          // out_w flat = p*1024 + a*32 + c
        int a = (idx >> 5) & 31;
        int c = idx & 31;
        g_W2[a * CP + c * PP + p] = out_w[idx];
    }
    if (idx < AA * HH) {
        int a = idx >> 8;           // in_w flat = a*256 + k
        int k = idx & 255;
        g_wT[k * AA + a] = in_w[idx];
    }
}

// ---------------------------------------------------------------------------
// K1: h[bi][a] = sum_k x[bi][k] * in_w[a][k] + in_b[a]
// One block per bi row. Tail also writes the [b][c][j] transpose for k_main.
// ---------------------------------------------------------------------------
__global__ void k_h(const float* __restrict__ x,
                    const float* __restrict__ in_b) {
    __shared__ float red[256];
    int t  = threadIdx.x;
    int bi = blockIdx.x;
    int a  = t & 31;
    int kc = t >> 5;                 // 0..7
    const float* xr = x + bi * HH + kc * 32;     // uniform per warp
    const float* wr = g_wT + (kc * 32) * AA + a; // coalesced over lanes
    float acc = 0.f;
#pragma unroll
    for (int k = 0; k < 32; k++)
        acc += xr[k] * wr[k * AA];
    red[t] = acc;
    __syncthreads();
    if (t < 32) {
        float s = in_b[t];
#pragma unroll
        for (int q = 0; q < 8; q++) s += red[q * 32 + t];
        g_h[bi * AA + t] = s;
        int b = bi >> 8, i = bi & 255;
        g_hT[b * (AA * LL) + t * LL + i] = s;    // transposed copy
    }
}

// ---------------------------------------------------------------------------
// K2: M[bi][cp] = sum_a h[bi][a] * W2[a][cp]
// ---------------------------------------------------------------------------
__global__ void k_m() {
    __shared__ float hs[16 * AA];    // 2 KB
    int t   = threadIdx.x;
    int bi0 = blockIdx.x * 16;
    int cp  = blockIdx.y * 256 + t;

    for (int idx = t; idx < 16 * AA; idx += 256)
        hs[idx] = g_h[bi0 * AA + idx];
    __syncthreads();

    float acc[16];
#pragma unroll
    for (int i = 0; i < 16; i++) acc[i] = 0.f;

#pragma unroll
    for (int a = 0; a < AA; a++) {
        float w = g_W2[a * CP + cp];
#pragma unroll
        for (int i = 0; i < 16; i++)
            acc[i] = fmaf(hs[i * AA + a], w, acc[i]);
    }
#pragma unroll
    for (int i = 0; i < 16; i++)
        g_M[(bi0 + i) * CP + cp] = acc[i];
}

// ---------------------------------------------------------------------------
// K3 (dominant): out[bi][j][p] = sum_c M[bi][c][p] * h[b][j][c] + table[d][p]
// One block per bi. Thread computes an 8j x 8p register tile:
//   pg = t & 7  -> p in [pg*8, pg*8+8)
//   jg = t >> 3 -> j in [jg*8, jg*8+8)
// Per c: 2 LDS.128 (M pairs as ulonglong2) + 2 LDS.128 (h float4 pair from
// the c-major hT tile) + 8 splat MOVs + 32 fma.rn.f32x2. LDS instr count is
// 4.25x lower than the 1x64 layout; fma pipe becomes the binder.
// ---------------------------------------------------------------------------
__global__ void __launch_bounds__(256, 2)
k_main(const float* __restrict__ pos_w,
       const float* __restrict__ pos_b,
       const float* __restrict__ out_b,
       float* __restrict__ out) {
    __shared__ __align__(16) float ms [AA * PP];   // M[c][p]      8 KB
    __shared__ __align__(16) float hts[AA * LL];   // hT[c][j]    32 KB
    __shared__ __align__(16) float ps [17 * 68];   // pos table  4.6 KB

    int t  = threadIdx.x;
    int bi = blockIdx.x;
    int b  = bi >> 8;
    int i  = bi & 255;

    // M slice for this (b,i): contiguous, coalesced
    for (int idx = t; idx < AA * PP; idx += 256)
        ms[idx] = g_M[bi * CP + idx];

    // hT tile: already c-major in gmem -> coalesced read, conflict-free write
    const float* hb = &g_hT[b * (AA * LL)];
#pragma unroll
    for (int k = 0; k < 32; k++)
        hts[k * 256 + t] = hb[k * 256 + t];

    // fold out_b + pos_b into pos table: ps[d][p]
    for (int idx = t; idx < 17 * 64; idx += 256) {
        int d = idx >> 6, p = idx & 63;
        ps[d * 68 + p] = pos_w[p * 17 + d] + pos_b[p] + out_b[p];
    }
    __syncthreads();

    int pg = t & 7;        // p-group (8 p)
    int jg = t >> 3;       // j-group (8 j)

    unsigned long long acc[32];    // [jj][k] : jj*4 + k, k over 4 p-pairs
#pragma unroll
    for (int k = 0; k < 32; k++) acc[k] = 0ULL;

    const ulonglong2* msv = reinterpret_cast<const ulonglong2*>(ms);
    const float4*     hv  = reinterpret_cast<const float4*>(hts);

#pragma unroll 8
    for (int c = 0; c < 32; c++) {
        // M[c][pg*8 .. pg*8+7]: float base = c*64 + pg*8 -> ull2 idx c*16+pg*2
        ulonglong2 ma = msv[c * 16 + pg * 2];
        ulonglong2 mb = msv[c * 16 + pg * 2 + 1];
        // h[c][jg*8 .. jg*8+7]: float base = c*256 + jg*8 -> float4 idx c*64+jg*2
        float4 h0 = hv[c * 64 + jg * 2];
        float4 h1 = hv[c * 64 + jg * 2 + 1];

        float hvals[8] = {h0.x, h0.y, h0.z, h0.w, h1.x, h1.y, h1.z, h1.w};
#pragma unroll
        for (int jj = 0; jj < 8; jj++) {
            unsigned int hu = __float_as_uint(hvals[jj]);
            unsigned long long h2;
            asm("mov.b64 %0, {%1, %1};" : "=l"(h2) : "r"(hu));
            asm("fma.rn.f32x2 %0, %1, %2, %0;" : "+l"(acc[jj*4+0]) : "l"(ma.x), "l"(h2));
            asm("fma.rn.f32x2 %0, %1, %2, %0;" : "+l"(acc[jj*4+1]) : "l"(ma.y), "l"(h2));
            asm("fma.rn.f32x2 %0, %1, %2, %0;" : "+l"(acc[jj*4+2]) : "l"(mb.x), "l"(h2));
            asm("fma.rn.f32x2 %0, %1, %2, %0;" : "+l"(acc[jj*4+3]) : "l"(mb.y), "l"(h2));
        }
    }

    // epilogue: packed add of rel-pos row, vectorized store
#pragma unroll
    for (int jj = 0; jj < 8; jj++) {
        int j = jg * 8 + jj;
        int d = i - j;
        d = (d < -8) ? -8 : ((d > 8) ? 8 : d);
        d += 8;
        const ulonglong2* pr =
            reinterpret_cast<const ulonglong2*>(&ps[d * 68 + pg * 8]);
        ulonglong2 p0 = pr[0], p1 = pr[1];
        ulonglong2 r0, r1;
        asm("add.rn.f32x2 %0, %1, %2;" : "=l"(r0.x) : "l"(acc[jj*4+0]), "l"(p0.x));
        asm("add.rn.f32x2 %0, %1, %2;" : "=l"(r0.y) : "l"(acc[jj*4+1]), "l"(p0.y));
        asm("add.rn.f32x2 %0, %1, %2;" : "=l"(r1.x) : "l"(acc[jj*4+2]), "l"(p1.x));
        asm("add.rn.f32x2 %0, %1, %2;" : "=l"(r1.y) : "l"(acc[jj*4+3]), "l"(p1.y));
        ulonglong2* ob = reinterpret_cast<ulonglong2*>(
            out + ((size_t)bi * LL + j) * PP + pg * 8);
        ob[0] = r0;
        ob[1] = r1;
    }
}

// ---------------------------------------------------------------------------
// Launch
// inputs (metadata order): inputs_embeds, in_w, in_b, out_w, out_b, pos_w, pos_b
// ---------------------------------------------------------------------------
extern "C" void kernel_launch(void* const* d_in, const int* in_sizes, int n_in,
                              void* d_out, int out_size) {
    const float* x     = (const float*)d_in[0];
    const float* in_w  = (const float*)d_in[1];
    const float* in_b  = (const float*)d_in[2];
    const float* out_w = (const float*)d_in[3];
    const float* out_b = (const float*)d_in[4];
    const float* pos_w = (const float*)d_in[5];
    const float* pos_b = (const float*)d_in[6];
    float* out = (float*)d_out;

    k_prep<<<256, 256>>>(out_w, in_w);
    k_h   <<<NBI, 256>>>(x, in_b);
    k_m   <<<dim3(32, 8), 256>>>();
    k_main<<<NBI, 256>>>(pos_w, pos_b, out_b, out);
}